// round 1
// baseline (speedup 1.0000x reference)
#include <cuda_runtime.h>

#define B_EX   16384
#define NEG    10
#define E_DIM  128
#define WARPS_PER_BLOCK 8
#define THREADS (WARPS_PER_BLOCK * 32)
#define NBLOCKS (B_EX / WARPS_PER_BLOCK)   // 2048

// Scratch: per-block partial sums (allocation-free __device__ global per rules)
__device__ float g_partials[NBLOCKS];

__device__ __forceinline__ float log_sigmoid(float x) {
    // stable: min(x,0) - log1p(exp(-|x|))
    return fminf(x, 0.0f) - log1pf(expf(-fabsf(x)));
}

__global__ void __launch_bounds__(THREADS)
w2v_neg_sampling_kernel(const int*    __restrict__ input_word,
                        const int*    __restrict__ context_word,
                        const int*    __restrict__ noise_words,
                        const float4* __restrict__ W_in,
                        const float4* __restrict__ W_ctx)
{
    const int lane    = threadIdx.x & 31;
    const int warp_in = threadIdx.x >> 5;
    const int b       = blockIdx.x * WARPS_PER_BLOCK + warp_in;   // example id

    // Row = 128 floats = 32 float4; lane l owns float4 #l of each row.
    const int ci = input_word[b];
    const int xi = context_word[b];

    // Issue all gathers early for MLP (center, ctx, 10 noise rows in flight).
    float4 c = W_in [(size_t)ci * 32 + lane];
    float4 x = W_ctx[(size_t)xi * 32 + lane];

    int nidx[NEG];
#pragma unroll
    for (int k = 0; k < NEG; k++) nidx[k] = noise_words[b * NEG + k];

    float4 nv[NEG];
#pragma unroll
    for (int k = 0; k < NEG; k++)
        nv[k] = W_ctx[(size_t)nidx[k] * 32 + lane];

    // Per-lane partial dot products.
    float pos = c.x * x.x + c.y * x.y + c.z * x.z + c.w * x.w;
    float neg[NEG];
#pragma unroll
    for (int k = 0; k < NEG; k++)
        neg[k] = c.x * nv[k].x + c.y * nv[k].y + c.z * nv[k].z + c.w * nv[k].w;

    // Warp reduce 11 values.
#pragma unroll
    for (int off = 16; off > 0; off >>= 1) {
        pos += __shfl_xor_sync(0xffffffffu, pos, off);
#pragma unroll
        for (int k = 0; k < NEG; k++)
            neg[k] += __shfl_xor_sync(0xffffffffu, neg[k], off);
    }

    // Per-example loss contribution: -( ls(pos) + sum_k ls(-neg_k) )
    __shared__ float s_warp[WARPS_PER_BLOCK];
    if (lane == 0) {
        float v = -log_sigmoid(pos);
#pragma unroll
        for (int k = 0; k < NEG; k++)
            v -= log_sigmoid(-neg[k]);
        s_warp[warp_in] = v;
    }
    __syncthreads();

    if (threadIdx.x == 0) {
        float t = 0.0f;
#pragma unroll
        for (int i = 0; i < WARPS_PER_BLOCK; i++) t += s_warp[i];
        g_partials[blockIdx.x] = t;
    }
}

// Deterministic final reduction of NBLOCKS partials -> scalar mean.
__global__ void __launch_bounds__(256)
w2v_finalize_kernel(float* __restrict__ out)
{
    __shared__ float s[256];
    float t = 0.0f;
    // fixed-order per-thread accumulation: deterministic across replays
    for (int i = threadIdx.x; i < NBLOCKS; i += 256)
        t += g_partials[i];
    s[threadIdx.x] = t;
    __syncthreads();
#pragma unroll
    for (int step = 128; step > 0; step >>= 1) {
        if (threadIdx.x < step) s[threadIdx.x] += s[threadIdx.x + step];
        __syncthreads();
    }
    if (threadIdx.x == 0)
        out[0] = s[0] / (float)B_EX;
}

extern "C" void kernel_launch(void* const* d_in, const int* in_sizes, int n_in,
                              void* d_out, int out_size)
{
    const int*    input_word   = (const int*)   d_in[0];
    const int*    context_word = (const int*)   d_in[1];
    const int*    noise_words  = (const int*)   d_in[2];
    const float4* W_in         = (const float4*)d_in[3];
    const float4* W_ctx        = (const float4*)d_in[4];
    float* out = (float*)d_out;

    w2v_neg_sampling_kernel<<<NBLOCKS, THREADS>>>(input_word, context_word,
                                                  noise_words, W_in, W_ctx);
    w2v_finalize_kernel<<<1, 256>>>(out);
}